// round 2
// baseline (speedup 1.0000x reference)
#include <cuda_runtime.h>
#include <math.h>

#define BATCH 16
#define CH    3
#define H     512
#define W     512
#define HW    (H * W)
#define KRAD  5
#define KSZ   11
#define EPS_LCS  1e-6f
#define EPS_PSNR 1e-8f

#define XS    128          // owned strip width
#define NSEG  8
#define SEG   (H / NSEG)   // 64 owned rows per block
#define NXS   (W / XS)     // 4

__device__ float g_mse[BATCH];     // zero-initialized at module load; finalize re-zeros
__device__ float g_cos_sum;

// ---------------------------------------------------------------------------
// Fused: products + MSE + horizontal 11-tap (smem, double-buffered) +
// vertical 11-tap (running sum + smem ring) + cosine + block reduce.
// grid = BATCH * NXS * NSEG, block = 128
// ---------------------------------------------------------------------------
__global__ void __launch_bounds__(128) k_fused(const float* __restrict__ pred,
                                               const float* __restrict__ tgt) {
    int bid = blockIdx.x;
    int seg = bid & 7;          // NSEG = 8
    int xs  = (bid >> 3) & 3;   // NXS = 4
    int b   = bid >> 5;

    int y0 = seg * SEG;
    int x0 = xs * XS;
    int tid = threadIdx.x;

    const float* pb = pred + (size_t)b * CH * HW;
    const float* tb = tgt  + (size_t)b * CH * HW;

    // product columns i = 0..137 map to gx = x0 - 5 + i
    int gx0 = x0 - KRAD + tid;          // i = tid
    int gx1 = gx0 + XS;                 // i = tid + 128 (tid < 10)
    bool v0 = (gx0 >= 0) && (gx0 < W);
    bool v1 = (tid < 10) && (gx1 < W);

    __shared__ float s_prod[2][3][144];     // [buf][xx,yy,xy][i]
    __shared__ float s_ring[3][KSZ][XS];    // vertical ring, thread-private columns
    __shared__ float s_redc[4], s_redm[4];

    float vxx = 0.f, vyy = 0.f, vxy = 0.f;
    float msum = 0.f, csum = 0.f;

    for (int it = 0; it < SEG + 2 * KRAD; it++) {
        int yc = y0 - KRAD + it;
        int bsel = it & 1;
        int ridx = it % KSZ;
        bool rowvalid = (yc >= 0) && (yc < H);
        bool rowowned = (yc >= y0) && (yc < y0 + SEG);

        if (rowvalid) {
            const float* prow = pb + (size_t)yc * W;
            const float* trow = tb + (size_t)yc * W;

            float pp = 0.f, tt = 0.f, xy = 0.f, ml = 0.f;
            if (v0) {
#pragma unroll
                for (int c = 0; c < CH; c++) {
                    float p = prow[c * HW + gx0];
                    float t = trow[c * HW + gx0];
                    pp += p * p; tt += t * t; xy += p * t;
                    float d = p - t; ml += d * d;
                }
            }
            s_prod[bsel][0][tid] = pp;
            s_prod[bsel][1][tid] = tt;
            s_prod[bsel][2][tid] = xy;
            if (rowowned && tid >= KRAD) msum += ml;   // owned cols: i in [5,133)

            if (tid < 10) {
                float pp1 = 0.f, tt1 = 0.f, xy1 = 0.f, ml1 = 0.f;
                if (v1) {
#pragma unroll
                    for (int c = 0; c < CH; c++) {
                        float p = prow[c * HW + gx1];
                        float t = trow[c * HW + gx1];
                        pp1 += p * p; tt1 += t * t; xy1 += p * t;
                        float d = p - t; ml1 += d * d;
                    }
                }
                s_prod[bsel][0][tid + XS] = pp1;
                s_prod[bsel][1][tid + XS] = tt1;
                s_prod[bsel][2][tid + XS] = xy1;
                if (rowowned && tid < KRAD) msum += ml1;  // i = tid+128 in [128,133)
            }
        }
        __syncthreads();   // orders this row's writes before reads; also protects buf reuse

        float hxx = 0.f, hyy = 0.f, hxy = 0.f;
        if (rowvalid) {
#pragma unroll
            for (int j = 0; j < KSZ; j++) {
                hxx += s_prod[bsel][0][tid + j];
                hyy += s_prod[bsel][1][tid + j];
                hxy += s_prod[bsel][2][tid + j];
            }
        }

        vxx += hxx; vyy += hyy; vxy += hxy;
        s_ring[0][ridx][tid] = hxx;
        s_ring[1][ridx][tid] = hyy;
        s_ring[2][ridx][tid] = hxy;

        int yo = yc - KRAD;
        if (yo >= y0) {
            float cosv = vxy / (sqrtf(vxx) * sqrtf(vyy) + EPS_LCS);
            csum += cosv;
            int sidx = (ridx + 1) % KSZ;     // row yo-5, leaving the window
            vxx -= s_ring[0][sidx][tid];
            vyy -= s_ring[1][sidx][tid];
            vxy -= s_ring[2][sidx][tid];
        }
    }

    // block reduction: warp shuffles, then 4 partials in smem
    int lane = tid & 31, wid = tid >> 5;
#pragma unroll
    for (int o = 16; o > 0; o >>= 1) {
        csum += __shfl_xor_sync(0xffffffffu, csum, o);
        msum += __shfl_xor_sync(0xffffffffu, msum, o);
    }
    if (lane == 0) { s_redc[wid] = csum; s_redm[wid] = msum; }
    __syncthreads();
    if (tid == 0) {
        float ct = s_redc[0] + s_redc[1] + s_redc[2] + s_redc[3];
        float mt = s_redm[0] + s_redm[1] + s_redm[2] + s_redm[3];
        atomicAdd(&g_cos_sum, ct);
        atomicAdd(&g_mse[b], mt);
    }
}

// ---------------------------------------------------------------------------
// Finalize (32 threads): PSNR + LCS, then re-zero accumulators for next replay
// ---------------------------------------------------------------------------
__global__ void k_finalize(float* __restrict__ out) {
    int t = threadIdx.x;
    float v = 0.f;
    if (t < BATCH) {
        float mse = g_mse[t] * (1.0f / (float)(CH * HW));
        v = logf(mse + EPS_PSNR);
    }
#pragma unroll
    for (int o = 16; o > 0; o >>= 1)
        v += __shfl_xor_sync(0xffffffffu, v, o);
    if (t == 0) {
        const float scale = 10.0f / logf(10.0f);
        float psnr_loss = scale * (v * (1.0f / (float)BATCH));
        float lcs_loss  = 1.0f - g_cos_sum * (1.0f / (float)(BATCH * HW));
        out[0] = psnr_loss + lcs_loss;
        g_cos_sum = 0.0f;
    }
    if (t < BATCH) g_mse[t] = 0.0f;
}

// ---------------------------------------------------------------------------
extern "C" void kernel_launch(void* const* d_in, const int* in_sizes, int n_in,
                              void* d_out, int out_size) {
    const float* pred = (const float*)d_in[0];
    const float* tgt  = (const float*)d_in[1];
    float* out = (float*)d_out;

    k_fused<<<BATCH * NXS * NSEG, XS>>>(pred, tgt);
    k_finalize<<<1, 32>>>(out);
}

// round 4
// speedup vs baseline: 2.2159x; 2.2159x over previous
#include <cuda_runtime.h>
#include <math.h>

#define BATCH 16
#define CH    3
#define H     512
#define W     512
#define HW    (H * W)
#define KRAD  5
#define EPS_LCS  1e-6f
#define EPS_PSNR 1e-8f

#define NSEG  32
#define SEG   (H / NSEG)            // 16 owned rows per pass-2 block
#define P2_BLOCKS (BATCH * NSEG)    // 512

__device__ float g_sxx[BATCH * HW];
__device__ float g_syy[BATCH * HW];
__device__ float g_sxy[BATCH * HW];
__device__ float g_mse[BATCH];      // zero at module load; last pass-2 block re-zeros
__device__ float g_cos_sum;
__device__ unsigned int g_count;

// ---------------------------------------------------------------------------
// Pass 1: one image row per block. Products + MSE + horizontal 11-tap.
// grid = BATCH*H = 8192, block = 128 (each thread 4 columns via float4)
// ---------------------------------------------------------------------------
__global__ void __launch_bounds__(128) k_pass1(const float* __restrict__ pred,
                                               const float* __restrict__ tgt) {
    int row = blockIdx.x;
    int b = row >> 9;
    int y = row & (H - 1);
    int tid = threadIdx.x;
    int x4 = tid << 2;

    const float* pr = pred + (size_t)b * CH * HW + (size_t)y * W;
    const float* tr = tgt  + (size_t)b * CH * HW + (size_t)y * W;

    float4 P0 = *(const float4*)(pr + x4);
    float4 P1 = *(const float4*)(pr + HW + x4);
    float4 P2 = *(const float4*)(pr + 2 * HW + x4);
    float4 T0 = *(const float4*)(tr + x4);
    float4 T1 = *(const float4*)(tr + HW + x4);
    float4 T2 = *(const float4*)(tr + 2 * HW + x4);

    // per-lane channel-summed products
    float xx0 = P0.x*P0.x + P1.x*P1.x + P2.x*P2.x;
    float xx1 = P0.y*P0.y + P1.y*P1.y + P2.y*P2.y;
    float xx2 = P0.z*P0.z + P1.z*P1.z + P2.z*P2.z;
    float xx3 = P0.w*P0.w + P1.w*P1.w + P2.w*P2.w;

    float yy0 = T0.x*T0.x + T1.x*T1.x + T2.x*T2.x;
    float yy1 = T0.y*T0.y + T1.y*T1.y + T2.y*T2.y;
    float yy2 = T0.z*T0.z + T1.z*T1.z + T2.z*T2.z;
    float yy3 = T0.w*T0.w + T1.w*T1.w + T2.w*T2.w;

    float xy0 = P0.x*T0.x + P1.x*T1.x + P2.x*T2.x;
    float xy1 = P0.y*T0.y + P1.y*T1.y + P2.y*T2.y;
    float xy2 = P0.z*T0.z + P1.z*T1.z + P2.z*T2.z;
    float xy3 = P0.w*T0.w + P1.w*T1.w + P2.w*T2.w;

    float d, msev = 0.f;
    d = P0.x - T0.x; msev += d * d;  d = P0.y - T0.y; msev += d * d;
    d = P0.z - T0.z; msev += d * d;  d = P0.w - T0.w; msev += d * d;
    d = P1.x - T1.x; msev += d * d;  d = P1.y - T1.y; msev += d * d;
    d = P1.z - T1.z; msev += d * d;  d = P1.w - T1.w; msev += d * d;
    d = P2.x - T2.x; msev += d * d;  d = P2.y - T2.y; msev += d * d;
    d = P2.z - T2.z; msev += d * d;  d = P2.w - T2.w; msev += d * d;

    // smem: 8-float left guard, W data, 12-float right guard (float4 aligned)
    __shared__ float sbuf[3][8 + W + 12];
    __shared__ float sred[4];

    float* a0 = &sbuf[0][8];
    float* a1 = &sbuf[1][8];
    float* a2 = &sbuf[2][8];

    if (tid < 8) { sbuf[0][tid] = 0.f; sbuf[1][tid] = 0.f; sbuf[2][tid] = 0.f; }
    if (tid < 12) {
        sbuf[0][8 + W + tid] = 0.f;
        sbuf[1][8 + W + tid] = 0.f;
        sbuf[2][8 + W + tid] = 0.f;
    }
    *(float4*)(a0 + x4) = make_float4(xx0, xx1, xx2, xx3);
    *(float4*)(a1 + x4) = make_float4(yy0, yy1, yy2, yy3);
    *(float4*)(a2 + x4) = make_float4(xy0, xy1, xy2, xy3);
    __syncthreads();

    size_t o = (size_t)b * HW + (size_t)y * W + x4;

    // horizontal 11-tap windows: read 20 consecutive floats as 5 float4s
    // v[m] = a[x4-8+m]; lane l window = v[l+3..l+13]
#define HWIN(a, dst)                                                         \
    {                                                                        \
        float4 q0 = *(const float4*)((a) + x4 - 8);                          \
        float4 q1 = *(const float4*)((a) + x4 - 4);                          \
        float4 q2 = *(const float4*)((a) + x4);                              \
        float4 q3 = *(const float4*)((a) + x4 + 4);                          \
        float4 q4 = *(const float4*)((a) + x4 + 8);                          \
        float w0 = q0.w + q1.x + q1.y + q1.z + q1.w                          \
                 + q2.x + q2.y + q2.z + q2.w + q3.x + q3.y;                  \
        float w1 = w0 + q3.z - q0.w;                                         \
        float w2 = w1 + q3.w - q1.x;                                         \
        float w3 = w2 + q4.x - q1.y;                                         \
        *(float4*)((dst) + o) = make_float4(w0, w1, w2, w3);                 \
    }

    HWIN(a0, g_sxx)
    HWIN(a1, g_syy)
    HWIN(a2, g_sxy)
#undef HWIN

    // block-reduce mse, one atomic per block
    int lane = tid & 31, wid = tid >> 5;
#pragma unroll
    for (int s = 16; s > 0; s >>= 1)
        msev += __shfl_xor_sync(0xffffffffu, msev, s);
    if (lane == 0) sred[wid] = msev;
    __syncthreads();
    if (tid == 0)
        atomicAdd(&g_mse[b], sred[0] + sred[1] + sred[2] + sred[3]);
}

// ---------------------------------------------------------------------------
// Pass 2: vertical 11-tap running sum + cosine + reduce + fused finalize.
// grid = BATCH*NSEG = 512, block = 256 (each thread a float2 column pair)
// ---------------------------------------------------------------------------
__global__ void __launch_bounds__(256) k_pass2(float* __restrict__ out) {
    int blk = blockIdx.x;
    int seg = blk & (NSEG - 1);
    int b   = blk >> 5;
    int y0  = seg * SEG;
    int tid = threadIdx.x;
    int x   = tid << 1;

    const float* pxx = g_sxx + (size_t)b * HW + x;
    const float* pyy = g_syy + (size_t)b * HW + x;
    const float* pxy = g_sxy + (size_t)b * HW + x;

    float axx0 = 0.f, axx1 = 0.f, ayy0 = 0.f, ayy1 = 0.f, axy0 = 0.f, axy1 = 0.f;

    // warm-up rows [y0-5, y0+4] (y0+4 <= 500 < H always)
    {
        int ylo = y0 - KRAD; if (ylo < 0) ylo = 0;
        for (int y = ylo; y < y0 + KRAD; y++) {
            size_t r = (size_t)y * W;
            float2 v;
            v = *(const float2*)(pxx + r); axx0 += v.x; axx1 += v.y;
            v = *(const float2*)(pyy + r); ayy0 += v.x; ayy1 += v.y;
            v = *(const float2*)(pxy + r); axy0 += v.x; axy1 += v.y;
        }
    }

    float csum = 0.f;
#pragma unroll 4
    for (int yy = y0; yy < y0 + SEG; yy++) {
        int ya = yy + KRAD;
        if (ya < H) {
            size_t r = (size_t)ya * W;
            float2 v;
            v = *(const float2*)(pxx + r); axx0 += v.x; axx1 += v.y;
            v = *(const float2*)(pyy + r); ayy0 += v.x; ayy1 += v.y;
            v = *(const float2*)(pxy + r); axy0 += v.x; axy1 += v.y;
        }
        csum += axy0 / (sqrtf(axx0) * sqrtf(ayy0) + EPS_LCS);
        csum += axy1 / (sqrtf(axx1) * sqrtf(ayy1) + EPS_LCS);
        int yr = yy - KRAD;
        if (yr >= 0) {
            size_t r = (size_t)yr * W;   // re-read from L2 (written 11 rows ago)
            float2 v;
            v = *(const float2*)(pxx + r); axx0 -= v.x; axx1 -= v.y;
            v = *(const float2*)(pyy + r); ayy0 -= v.x; ayy1 -= v.y;
            v = *(const float2*)(pxy + r); axy0 -= v.x; axy1 -= v.y;
        }
    }

    // block reduce csum
    __shared__ float sred[8];
    int lane = tid & 31, wid = tid >> 5;
#pragma unroll
    for (int s = 16; s > 0; s >>= 1)
        csum += __shfl_xor_sync(0xffffffffu, csum, s);
    if (lane == 0) sred[wid] = csum;
    __syncthreads();
    if (tid == 0) {
        float t = sred[0] + sred[1] + sred[2] + sred[3]
                + sred[4] + sred[5] + sred[6] + sred[7];
        atomicAdd(&g_cos_sum, t);
    }

    // last-block fused finalize (threadfence + counter)
    __shared__ unsigned int amLast;
    if (tid == 0) {
        __threadfence();
        amLast = (atomicAdd(&g_count, 1u) == (unsigned)(P2_BLOCKS - 1));
    }
    __syncthreads();
    if (amLast && tid < 32) {
        float v = 0.f;
        if (tid < BATCH)
            v = logf(g_mse[tid] * (1.0f / (float)(CH * HW)) + EPS_PSNR);
#pragma unroll
        for (int s = 16; s > 0; s >>= 1)
            v += __shfl_xor_sync(0xffffffffu, v, s);
        if (tid == 0) {
            const float scale = 10.0f / logf(10.0f);
            float psnr_loss = scale * (v * (1.0f / (float)BATCH));
            float lcs_loss  = 1.0f - g_cos_sum * (1.0f / (float)(BATCH * HW));
            out[0] = psnr_loss + lcs_loss;
            g_cos_sum = 0.0f;
            g_count = 0u;
        }
        if (tid < BATCH) g_mse[tid] = 0.0f;
    }
}

// ---------------------------------------------------------------------------
extern "C" void kernel_launch(void* const* d_in, const int* in_sizes, int n_in,
                              void* d_out, int out_size) {
    const float* pred = (const float*)d_in[0];
    const float* tgt  = (const float*)d_in[1];
    float* out = (float*)d_out;

    k_pass1<<<BATCH * H, 128>>>(pred, tgt);
    k_pass2<<<P2_BLOCKS, 256>>>(out);
}